// round 3
// baseline (speedup 1.0000x reference)
#include <cuda_runtime.h>
#include <cstddef>

#define BB   2
#define LL   512
#define HH   128
#define NH   8
#define HD   16
#define SCS  516   // padded score row stride (bank-conflict-free across heads)

// ---------------- scratch (static device globals; no allocs) ----------------
__device__ float g_q  [BB*LL*HH];            // Q projection        [b,l,128]
__device__ float g_ka [BB*LL*HH];            // K + abs_pos_k       [b,l,128]
__device__ float g_va [BB*LL*HH];            // V + abs_pos_v       [b,l,128]
__device__ float g_S0 [(size_t)BB*LL*NH*LL]; // base scores         [b,q,h,k]  16MB
__device__ float g_P  [(size_t)BB*NH*LL*LL]; // probs               [b,h,q,k]  16MB
__device__ float g_ctx[BB*LL*HH];            // context (pre-Wo)    [b,q,128]

// ---------------- kernel 1: QKV projections + abs-pos folds ----------------
__global__ void __launch_bounds__(128) k_proj(
    const float* __restrict__ x,  const float* __restrict__ apk,
    const float* __restrict__ apv,
    const float* __restrict__ Wq, const float* __restrict__ bq,
    const float* __restrict__ Wk, const float* __restrict__ bk,
    const float* __restrict__ Wv, const float* __restrict__ bv)
{
    int bl = blockIdx.x;          // (b*L + l), 0..1023
    int j  = threadIdx.x;         // output dim 0..127
    __shared__ float xs[HH];
    xs[j] = x[bl*HH + j];
    __syncthreads();
    float aq = bq[j], ak = bk[j], av = bv[j];
#pragma unroll 8
    for (int i = 0; i < HH; i++) {
        float xv = xs[i];
        aq = fmaf(xv, Wq[i*HH + j], aq);
        ak = fmaf(xv, Wk[i*HH + j], ak);
        av = fmaf(xv, Wv[i*HH + j], av);
    }
    g_q [bl*HH + j] = aq;
    g_ka[bl*HH + j] = ak + apk[bl*HH + j];
    g_va[bl*HH + j] = av + apv[bl*HH + j];
}

// ---------------- kernel 2: S0[b,q,h,k] = sum_d Q[b,q,h,d]*KA[b,k,h,d] -----
__global__ void __launch_bounds__(256) k_s0()
{
    int kt = blockIdx.x;          // k tile 0..7 (64 wide)
    int qt = blockIdx.y;          // q tile 0..7
    int bh = blockIdx.z;          // 0..15
    int b = bh >> 3, h = bh & 7;
    __shared__ float Qs[64][17];
    __shared__ float Ks[64][17];
    int t = threadIdx.x;
    {
        int row = t >> 2, c = (t & 3) * 4;
        float4 v = *reinterpret_cast<const float4*>(
            &g_q[((size_t)(b*LL) + qt*64 + row)*HH + h*HD + c]);
        Qs[row][c] = v.x; Qs[row][c+1] = v.y; Qs[row][c+2] = v.z; Qs[row][c+3] = v.w;
        float4 u = *reinterpret_cast<const float4*>(
            &g_ka[((size_t)(b*LL) + kt*64 + row)*HH + h*HD + c]);
        Ks[row][c] = u.x; Ks[row][c+1] = u.y; Ks[row][c+2] = u.z; Ks[row][c+3] = u.w;
    }
    __syncthreads();
    int tq = t >> 4, tk = t & 15;   // 16x16 thread grid, 4x4 outputs each
    float acc[4][4];
#pragma unroll
    for (int i = 0; i < 4; i++)
#pragma unroll
        for (int j = 0; j < 4; j++) acc[i][j] = 0.f;
#pragma unroll
    for (int d = 0; d < HD; d++) {
        float qr[4], kr[4];
#pragma unroll
        for (int i = 0; i < 4; i++) qr[i] = Qs[tq*4 + i][d];
#pragma unroll
        for (int j = 0; j < 4; j++) kr[j] = Ks[tk*4 + j][d];
#pragma unroll
        for (int i = 0; i < 4; i++)
#pragma unroll
            for (int j = 0; j < 4; j++) acc[i][j] = fmaf(qr[i], kr[j], acc[i][j]);
    }
#pragma unroll
    for (int i = 0; i < 4; i++) {
        int q = qt*64 + tq*4 + i;
        int k = kt*64 + tk*4;
        float4 o = make_float4(acc[i][0], acc[i][1], acc[i][2], acc[i][3]);
        *reinterpret_cast<float4*>(
            &g_S0[(((size_t)(b*LL + q))*NH + h)*LL + k]) = o;
    }
}

// ---------------- kernel 3: fused time_k stream -> softmax -> time_v stream
__global__ void __launch_bounds__(256) k_fused(
    const float* __restrict__ time_k,
    const float* __restrict__ time_v,
    const float* __restrict__ mask)
{
    int bq = blockIdx.x;                 // b*L + q
    int b  = bq >> 9, q = bq & 511;
    __shared__ __align__(16) float qs[HH];
    __shared__ float ms[LL];
    __shared__ __align__(16) float sc[NH*SCS];   // scores -> probs
    __shared__ float4 accbuf[8*32];

    int t = threadIdx.x, w = t >> 5, l = t & 31;

    if (t < HH) qs[t] = g_q[(size_t)bq*HH + t];
    {
        const float* mrow = mask + ((size_t)b*LL + q)*LL;
        for (int k = t; k < LL; k += 256) ms[k] = mrow[k];
    }
    {   // preload S0 row (contiguous 16KB) into padded smem
        const float4* s0p = reinterpret_cast<const float4*>(g_S0 + (size_t)bq*NH*LL);
        for (int i = t; i < 1024; i += 256) {
            int hh = i >> 7, kk = i & 127;
            reinterpret_cast<float4*>(sc + hh*SCS)[kk] = s0p[i];
        }
    }
    __syncthreads();

    int h  = l >> 2;
    int hb = h * SCS;
    int k0 = w * 64;
    float4 qv = reinterpret_cast<const float4*>(qs)[l];

    // ---- phase B: stream time_k, accumulate q.tk per (h,k) ----
    {
        const float4* tkb = reinterpret_cast<const float4*>(
            time_k + (size_t)bq * (LL*HH)) + l;
        for (int k = k0; k < k0 + 64; k += 4) {
            float4 a0 = tkb[(size_t)(k+0)*32];
            float4 a1 = tkb[(size_t)(k+1)*32];
            float4 a2 = tkb[(size_t)(k+2)*32];
            float4 a3 = tkb[(size_t)(k+3)*32];
            float p0 = a0.x*qv.x + a0.y*qv.y + a0.z*qv.z + a0.w*qv.w;
            float p1 = a1.x*qv.x + a1.y*qv.y + a1.z*qv.z + a1.w*qv.w;
            float p2 = a2.x*qv.x + a2.y*qv.y + a2.z*qv.z + a2.w*qv.w;
            float p3 = a3.x*qv.x + a3.y*qv.y + a3.z*qv.z + a3.w*qv.w;
            p0 += __shfl_xor_sync(0xffffffffu, p0, 1);
            p0 += __shfl_xor_sync(0xffffffffu, p0, 2);
            p1 += __shfl_xor_sync(0xffffffffu, p1, 1);
            p1 += __shfl_xor_sync(0xffffffffu, p1, 2);
            p2 += __shfl_xor_sync(0xffffffffu, p2, 1);
            p2 += __shfl_xor_sync(0xffffffffu, p2, 2);
            p3 += __shfl_xor_sync(0xffffffffu, p3, 1);
            p3 += __shfl_xor_sync(0xffffffffu, p3, 2);
            if ((l & 3) == 0) {
                sc[hb+k  ] = (sc[hb+k  ] + p0) * 0.25f + ms[k  ];
                sc[hb+k+1] = (sc[hb+k+1] + p1) * 0.25f + ms[k+1];
                sc[hb+k+2] = (sc[hb+k+2] + p2) * 0.25f + ms[k+2];
                sc[hb+k+3] = (sc[hb+k+3] + p3) * 0.25f + ms[k+3];
            }
        }
    }
    __syncthreads();

    // ---- phase C: softmax, one warp per head; also write probs to gmem ----
    {
        int hh = w;
        float* row = sc + hh * SCS;
        float mx = -1e30f;
        for (int k = l; k < LL; k += 32) mx = fmaxf(mx, row[k]);
#pragma unroll
        for (int o = 16; o; o >>= 1) mx = fmaxf(mx, __shfl_xor_sync(0xffffffffu, mx, o));
        float s = 0.f;
        for (int k = l; k < LL; k += 32) {
            float e = __expf(row[k] - mx);
            row[k] = e; s += e;
        }
#pragma unroll
        for (int o = 16; o; o >>= 1) s += __shfl_xor_sync(0xffffffffu, s, o);
        float inv = 1.f / s;
        float* Pr = g_P + (((size_t)(b*NH + hh)*LL + q) * LL);
        for (int k = l; k < LL; k += 32) {
            float p = row[k] * inv;
            row[k] = p;
            Pr[k] = p;
        }
    }
    __syncthreads();

    // ---- phase D: stream time_v, accumulate P.tv ----
    {
        const float4* tvb = reinterpret_cast<const float4*>(
            time_v + (size_t)bq * (LL*HH)) + l;
        float4 acc = make_float4(0.f, 0.f, 0.f, 0.f);
        for (int k = k0; k < k0 + 64; k += 4) {
            float4 a0 = tvb[(size_t)(k+0)*32];
            float4 a1 = tvb[(size_t)(k+1)*32];
            float4 a2 = tvb[(size_t)(k+2)*32];
            float4 a3 = tvb[(size_t)(k+3)*32];
            float p0 = sc[hb+k], p1 = sc[hb+k+1], p2 = sc[hb+k+2], p3 = sc[hb+k+3];
            acc.x = fmaf(p0,a0.x, fmaf(p1,a1.x, fmaf(p2,a2.x, fmaf(p3,a3.x, acc.x))));
            acc.y = fmaf(p0,a0.y, fmaf(p1,a1.y, fmaf(p2,a2.y, fmaf(p3,a3.y, acc.y))));
            acc.z = fmaf(p0,a0.z, fmaf(p1,a1.z, fmaf(p2,a2.z, fmaf(p3,a3.z, acc.z))));
            acc.w = fmaf(p0,a0.w, fmaf(p1,a1.w, fmaf(p2,a2.w, fmaf(p3,a3.w, acc.w))));
        }
        accbuf[w*32 + l] = acc;
    }
    __syncthreads();
    if (t < 32) {
        float4 s = accbuf[t];
#pragma unroll
        for (int ww = 1; ww < 8; ww++) {
            float4 u = accbuf[ww*32 + t];
            s.x += u.x; s.y += u.y; s.z += u.z; s.w += u.w;
        }
        reinterpret_cast<float4*>(g_ctx + (size_t)bq*HH)[t] = s;
    }
}

// ---------------- kernel 4: ctx += P @ (v + abs_v) --------------------------
__global__ void __launch_bounds__(256) k_pv()
{
    int qt = blockIdx.x;         // 0..7
    int bh = blockIdx.y;         // 0..15
    int b = bh >> 3, h = bh & 7;
    __shared__ float vs[LL*HD];  // 32KB head slice of va
    int t = threadIdx.x;
    {
        int row = t >> 2, c = (t & 3) * 4;
        for (int r0 = 0; r0 < LL; r0 += 64) {
            float4 v = *reinterpret_cast<const float4*>(
                &g_va[((size_t)(b*LL) + r0 + row)*HH + h*HD + c]);
            *reinterpret_cast<float4*>(&vs[(r0 + row)*HD + c]) = v;
        }
    }
    __syncthreads();
    int r  = t >> 2;             // q row in tile
    int d0 = (t & 3) * 4;
    const float4* Pr = reinterpret_cast<const float4*>(
        g_P + (((size_t)(b*NH + h)*LL + qt*64 + r) * LL));
    float4 acc = make_float4(0.f, 0.f, 0.f, 0.f);
#pragma unroll 4
    for (int k4 = 0; k4 < LL/4; k4++) {
        float4 p = Pr[k4];
        float4 v0 = *reinterpret_cast<const float4*>(&vs[(k4*4+0)*HD + d0]);
        float4 v1 = *reinterpret_cast<const float4*>(&vs[(k4*4+1)*HD + d0]);
        float4 v2 = *reinterpret_cast<const float4*>(&vs[(k4*4+2)*HD + d0]);
        float4 v3 = *reinterpret_cast<const float4*>(&vs[(k4*4+3)*HD + d0]);
        acc.x = fmaf(p.x,v0.x, fmaf(p.y,v1.x, fmaf(p.z,v2.x, fmaf(p.w,v3.x, acc.x))));
        acc.y = fmaf(p.x,v0.y, fmaf(p.y,v1.y, fmaf(p.z,v2.y, fmaf(p.w,v3.y, acc.y))));
        acc.z = fmaf(p.x,v0.z, fmaf(p.y,v1.z, fmaf(p.z,v2.z, fmaf(p.w,v3.z, acc.z))));
        acc.w = fmaf(p.x,v0.w, fmaf(p.y,v1.w, fmaf(p.z,v2.w, fmaf(p.w,v3.w, acc.w))));
    }
    float* cp = &g_ctx[((size_t)(b*LL) + qt*64 + r)*HH + h*HD + d0];
    float4 c = *reinterpret_cast<float4*>(cp);
    c.x += acc.x; c.y += acc.y; c.z += acc.z; c.w += acc.w;
    *reinterpret_cast<float4*>(cp) = c;
}

// ---------------- kernel 5: out = ctx @ Wo + bo -----------------------------
__global__ void __launch_bounds__(128) k_out(
    const float* __restrict__ Wo, const float* __restrict__ bo,
    float* __restrict__ out)
{
    int bl = blockIdx.x;
    int j  = threadIdx.x;
    __shared__ float cs[HH];
    cs[j] = g_ctx[(size_t)bl*HH + j];
    __syncthreads();
    float a = bo[j];
#pragma unroll 8
    for (int i = 0; i < HH; i++) a = fmaf(cs[i], Wo[i*HH + j], a);
    out[(size_t)bl*HH + j] = a;
}

// ---------------- launch ----------------------------------------------------
extern "C" void kernel_launch(void* const* d_in, const int* in_sizes, int n_in,
                              void* d_out, int out_size)
{
    const float* x      = (const float*)d_in[0];
    const float* time_k = (const float*)d_in[1];
    const float* time_v = (const float*)d_in[2];
    const float* apk    = (const float*)d_in[3];
    const float* apv    = (const float*)d_in[4];
    const float* mask   = (const float*)d_in[5];
    const float* Wq     = (const float*)d_in[6];
    const float* bq     = (const float*)d_in[7];
    const float* Wk     = (const float*)d_in[8];
    const float* bk     = (const float*)d_in[9];
    const float* Wv     = (const float*)d_in[10];
    const float* bv     = (const float*)d_in[11];
    const float* Wo     = (const float*)d_in[12];
    const float* bo     = (const float*)d_in[13];

    k_proj<<<BB*LL, 128>>>(x, apk, apv, Wq, bq, Wk, bk, Wv, bv);
    {
        dim3 g(8, 8, 16);
        k_s0<<<g, 256>>>();
    }
    k_fused<<<BB*LL, 256>>>(time_k, time_v, mask);
    {
        dim3 g(8, 16);
        k_pv<<<g, 256>>>();
    }
    k_out<<<BB*LL, 128>>>(Wo, bo, (float*)d_out);
}

// round 4
// speedup vs baseline: 1.1843x; 1.1843x over previous
#include <cuda_runtime.h>
#include <cstddef>

#define BB   2
#define LL   512
#define HH   128
#define NH   8
#define HD   16
#define SCS  516   // padded score row stride

// ---------------- scratch (static device globals; no allocs) ----------------
__device__ float g_q  [BB*LL*HH];            // Q projection        [b,l,128]
__device__ float g_ka [BB*LL*HH];            // K + abs_pos_k       [b,l,128]
__device__ float g_va [BB*LL*HH];            // V + abs_pos_v       [b,l,128]
__device__ float g_ctx[BB*LL*HH];            // context (pre-Wo)    [b,q,128]

// ---------------- kernel 1: QKV projections + abs-pos folds ----------------
__global__ void __launch_bounds__(128) k_proj(
    const float* __restrict__ x,  const float* __restrict__ apk,
    const float* __restrict__ apv,
    const float* __restrict__ Wq, const float* __restrict__ bq,
    const float* __restrict__ Wk, const float* __restrict__ bk,
    const float* __restrict__ Wv, const float* __restrict__ bv)
{
    int bl = blockIdx.x;          // (b*L + l), 0..1023
    int j  = threadIdx.x;         // output dim 0..127
    __shared__ float xs[HH];
    xs[j] = x[bl*HH + j];
    __syncthreads();
    float aq = bq[j], ak = bk[j], av = bv[j];
#pragma unroll 8
    for (int i = 0; i < HH; i++) {
        float xv = xs[i];
        aq = fmaf(xv, Wq[i*HH + j], aq);
        ak = fmaf(xv, Wk[i*HH + j], ak);
        av = fmaf(xv, Wv[i*HH + j], av);
    }
    g_q [bl*HH + j] = aq;
    g_ka[bl*HH + j] = ak + apk[bl*HH + j];
    g_va[bl*HH + j] = av + apv[bl*HH + j];
}

// ---------------- kernel 2: fully fused attention per (b,q) -----------------
// phase B: scores[h][k] = (q . (ka[k] + tk[k])) / 4 + mask[k]
// phase C: softmax per head (in smem, never leaves the block)
// phase D: ctx = sum_k P[h][k] * (va[k] + tv[k])
__global__ void __launch_bounds__(256) k_fused(
    const float* __restrict__ time_k,
    const float* __restrict__ time_v,
    const float* __restrict__ mask)
{
    int bq = blockIdx.x;                 // b*L + q
    int b  = bq >> 9, q = bq & 511;
    __shared__ __align__(16) float qs[HH];
    __shared__ float ms[LL];
    __shared__ __align__(16) float sc[NH*SCS];   // scores -> probs
    __shared__ float4 accbuf[8*32];

    int t = threadIdx.x, w = t >> 5, l = t & 31;

    if (t < HH) qs[t] = g_q[(size_t)bq*HH + t];
    {
        const float* mrow = mask + ((size_t)b*LL + q)*LL;
        for (int k = t; k < LL; k += 256) ms[k] = mrow[k];
    }
    __syncthreads();

    int h  = l >> 2;
    int hb = h * SCS;
    int k0 = w * 64;
    float4 qv = reinterpret_cast<const float4*>(qs)[l];

    const float4* kab = reinterpret_cast<const float4*>(g_ka + (size_t)b*(LL*HH)) + l;
    const float4* vab = reinterpret_cast<const float4*>(g_va + (size_t)b*(LL*HH)) + l;

    // ---- phase B: stream time_k (+ka from L2), accumulate scores ----
    {
        const float4* tkb = reinterpret_cast<const float4*>(
            time_k + (size_t)bq * (LL*HH)) + l;
        for (int k = k0; k < k0 + 64; k += 4) {
            float4 a0 = tkb[(size_t)(k+0)*32];
            float4 a1 = tkb[(size_t)(k+1)*32];
            float4 a2 = tkb[(size_t)(k+2)*32];
            float4 a3 = tkb[(size_t)(k+3)*32];
            float4 c0 = kab[(size_t)(k+0)*32];
            float4 c1 = kab[(size_t)(k+1)*32];
            float4 c2 = kab[(size_t)(k+2)*32];
            float4 c3 = kab[(size_t)(k+3)*32];
            float p0 = (a0.x+c0.x)*qv.x + (a0.y+c0.y)*qv.y
                     + (a0.z+c0.z)*qv.z + (a0.w+c0.w)*qv.w;
            float p1 = (a1.x+c1.x)*qv.x + (a1.y+c1.y)*qv.y
                     + (a1.z+c1.z)*qv.z + (a1.w+c1.w)*qv.w;
            float p2 = (a2.x+c2.x)*qv.x + (a2.y+c2.y)*qv.y
                     + (a2.z+c2.z)*qv.z + (a2.w+c2.w)*qv.w;
            float p3 = (a3.x+c3.x)*qv.x + (a3.y+c3.y)*qv.y
                     + (a3.z+c3.z)*qv.z + (a3.w+c3.w)*qv.w;
            p0 += __shfl_xor_sync(0xffffffffu, p0, 1);
            p0 += __shfl_xor_sync(0xffffffffu, p0, 2);
            p1 += __shfl_xor_sync(0xffffffffu, p1, 1);
            p1 += __shfl_xor_sync(0xffffffffu, p1, 2);
            p2 += __shfl_xor_sync(0xffffffffu, p2, 1);
            p2 += __shfl_xor_sync(0xffffffffu, p2, 2);
            p3 += __shfl_xor_sync(0xffffffffu, p3, 1);
            p3 += __shfl_xor_sync(0xffffffffu, p3, 2);
            if ((l & 3) == 0) {
                sc[hb+k  ] = p0 * 0.25f + ms[k  ];
                sc[hb+k+1] = p1 * 0.25f + ms[k+1];
                sc[hb+k+2] = p2 * 0.25f + ms[k+2];
                sc[hb+k+3] = p3 * 0.25f + ms[k+3];
            }
        }
    }
    __syncthreads();

    // ---- phase C: softmax, one warp per head (stays in smem) ----
    {
        float* row = sc + w * SCS;
        float mx = -1e30f;
        for (int k = l; k < LL; k += 32) mx = fmaxf(mx, row[k]);
#pragma unroll
        for (int o = 16; o; o >>= 1) mx = fmaxf(mx, __shfl_xor_sync(0xffffffffu, mx, o));
        float s = 0.f;
        for (int k = l; k < LL; k += 32) {
            float e = __expf(row[k] - mx);
            row[k] = e; s += e;
        }
#pragma unroll
        for (int o = 16; o; o >>= 1) s += __shfl_xor_sync(0xffffffffu, s, o);
        float inv = 1.f / s;
        for (int k = l; k < LL; k += 32) row[k] *= inv;
    }
    __syncthreads();

    // ---- phase D: stream time_v (+va from L2), accumulate P.(tv+va) ----
    {
        const float4* tvb = reinterpret_cast<const float4*>(
            time_v + (size_t)bq * (LL*HH)) + l;
        float4 accA = make_float4(0.f, 0.f, 0.f, 0.f);
        float4 accB = make_float4(0.f, 0.f, 0.f, 0.f);
        for (int k = k0; k < k0 + 64; k += 4) {
            float4 a0 = tvb[(size_t)(k+0)*32];
            float4 a1 = tvb[(size_t)(k+1)*32];
            float4 a2 = tvb[(size_t)(k+2)*32];
            float4 a3 = tvb[(size_t)(k+3)*32];
            float4 c0 = vab[(size_t)(k+0)*32];
            float4 c1 = vab[(size_t)(k+1)*32];
            float4 c2 = vab[(size_t)(k+2)*32];
            float4 c3 = vab[(size_t)(k+3)*32];
            float p0 = sc[hb+k], p1 = sc[hb+k+1], p2 = sc[hb+k+2], p3 = sc[hb+k+3];
            accA.x = fmaf(p0, a0.x+c0.x, fmaf(p1, a1.x+c1.x, accA.x));
            accA.y = fmaf(p0, a0.y+c0.y, fmaf(p1, a1.y+c1.y, accA.y));
            accA.z = fmaf(p0, a0.z+c0.z, fmaf(p1, a1.z+c1.z, accA.z));
            accA.w = fmaf(p0, a0.w+c0.w, fmaf(p1, a1.w+c1.w, accA.w));
            accB.x = fmaf(p2, a2.x+c2.x, fmaf(p3, a3.x+c3.x, accB.x));
            accB.y = fmaf(p2, a2.y+c2.y, fmaf(p3, a3.y+c3.y, accB.y));
            accB.z = fmaf(p2, a2.z+c2.z, fmaf(p3, a3.z+c3.z, accB.z));
            accB.w = fmaf(p2, a2.w+c2.w, fmaf(p3, a3.w+c3.w, accB.w));
        }
        accA.x += accB.x; accA.y += accB.y; accA.z += accB.z; accA.w += accB.w;
        accbuf[w*32 + l] = accA;
    }
    __syncthreads();
    if (t < 32) {
        float4 s = accbuf[t];
#pragma unroll
        for (int ww = 1; ww < 8; ww++) {
            float4 u = accbuf[ww*32 + t];
            s.x += u.x; s.y += u.y; s.z += u.z; s.w += u.w;
        }
        reinterpret_cast<float4*>(g_ctx + (size_t)bq*HH)[t] = s;
    }
}

// ---------------- kernel 3: out = ctx @ Wo + bo -----------------------------
__global__ void __launch_bounds__(128) k_out(
    const float* __restrict__ Wo, const float* __restrict__ bo,
    float* __restrict__ out)
{
    int bl = blockIdx.x;
    int j  = threadIdx.x;
    __shared__ float cs[HH];
    cs[j] = g_ctx[(size_t)bl*HH + j];
    __syncthreads();
    float a = bo[j];
#pragma unroll 8
    for (int i = 0; i < HH; i++) a = fmaf(cs[i], Wo[i*HH + j], a);
    out[(size_t)bl*HH + j] = a;
}

// ---------------- launch ----------------------------------------------------
extern "C" void kernel_launch(void* const* d_in, const int* in_sizes, int n_in,
                              void* d_out, int out_size)
{
    const float* x      = (const float*)d_in[0];
    const float* time_k = (const float*)d_in[1];
    const float* time_v = (const float*)d_in[2];
    const float* apk    = (const float*)d_in[3];
    const float* apv    = (const float*)d_in[4];
    const float* mask   = (const float*)d_in[5];
    const float* Wq     = (const float*)d_in[6];
    const float* bq     = (const float*)d_in[7];
    const float* Wk     = (const float*)d_in[8];
    const float* bk     = (const float*)d_in[9];
    const float* Wv     = (const float*)d_in[10];
    const float* bv     = (const float*)d_in[11];
    const float* Wo     = (const float*)d_in[12];
    const float* bo     = (const float*)d_in[13];

    k_proj<<<BB*LL, 128>>>(x, apk, apv, Wq, bq, Wk, bk, Wv, bv);
    k_fused<<<BB*LL, 256>>>(time_k, time_v, mask);
    k_out<<<BB*LL, 128>>>(Wo, bo, (float*)d_out);
}